// round 1
// baseline (speedup 1.0000x reference)
#include <cuda_runtime.h>

// ---------------------------------------------------------------------------
// GAFM: softmax over a singleton axis == 1, so the attention MLP (Wa/ba/Wh/bh)
// is algebraically dead. The model reduces to:
//   hop0: agg0[j] = FM(renorm(E[nbr0[j,:]])) + renorm(E[node_ids0[j]])
//   hop1: items   = FM(agg0[nbr1_idx[i,:]]) + renorm(E[item_ids[i]])
//         logit_i = sigmoid(<renorm(U[u[i]]), items>)
// FM(x) over 32 neighbors per dim: (sum x)^2 - sum x^2.
// renorm(e) = e * min(1, 1/||e||) (max_norm=1 embedding).
// ---------------------------------------------------------------------------

constexpr int K    = 64;
constexpr int B    = 2048;
constexpr int DEG  = 32;
constexpr int N0   = B * DEG;   // 65536

// 16 MB scratch for hop-0 aggregates (device global: allocation-guard safe).
__device__ float g_agg0[(size_t)N0 * K];

__device__ __forceinline__ float warp_sum(float v) {
#pragma unroll
    for (int o = 16; o; o >>= 1) v += __shfl_xor_sync(0xffffffffu, v, o);
    return v;
}

// One warp per hop-0 frontier node. Each lane owns dims {2*lane, 2*lane+1}.
__global__ void __launch_bounds__(256) hop0_kernel(
    const float* __restrict__ ent,
    const int*   __restrict__ node_ids0,
    const int*   __restrict__ nbr0)
{
    int warp = (blockIdx.x * blockDim.x + threadIdx.x) >> 5;
    int lane = threadIdx.x & 31;
    if (warp >= N0) return;

    // lane i holds neighbor index i; broadcast per-iteration via shfl.
    int myn = __ldg(nbr0 + warp * DEG + lane);

    float s0 = 0.f, s1 = 0.f, q0 = 0.f, q1 = 0.f;
#pragma unroll 4
    for (int g = 0; g < DEG; ++g) {
        int idx = __shfl_sync(0xffffffffu, myn, g);
        float2 v = __ldg((const float2*)(ent + (size_t)idx * K) + lane);
        float ss = warp_sum(v.x * v.x + v.y * v.y);          // ||row||^2
        float sc = ss > 1.f ? rsqrtf(ss) : 1.f;               // min(1, 1/||row||)
        float x0 = v.x * sc, x1 = v.y * sc;
        s0 += x0; s1 += x1;
        q0 += x0 * x0; q1 += x1 * x1;
    }

    // target node lookup + renorm
    int nid = __ldg(node_ids0 + warp);
    float2 t = __ldg((const float2*)(ent + (size_t)nid * K) + lane);
    float ts  = warp_sum(t.x * t.x + t.y * t.y);
    float tsc = ts > 1.f ? rsqrtf(ts) : 1.f;

    float2 o;
    o.x = s0 * s0 - q0 + t.x * tsc;
    o.y = s1 * s1 - q1 + t.y * tsc;
    ((float2*)(g_agg0 + (size_t)warp * K))[lane] = o;
}

// One warp per batch item.
__global__ void __launch_bounds__(256) hop1_kernel(
    const float* __restrict__ ent,
    const float* __restrict__ uemb,
    const int*   __restrict__ u,
    const int*   __restrict__ item_ids,
    const int*   __restrict__ nbr1,
    float*       __restrict__ out)
{
    int warp = (blockIdx.x * blockDim.x + threadIdx.x) >> 5;
    int lane = threadIdx.x & 31;
    if (warp >= B) return;

    int myn = __ldg(nbr1 + warp * DEG + lane);

    // FM over gathered hop-0 aggregates (no renorm on this gather).
    float s0 = 0.f, s1 = 0.f, q0 = 0.f, q1 = 0.f;
#pragma unroll 4
    for (int g = 0; g < DEG; ++g) {
        int idx = __shfl_sync(0xffffffffu, myn, g);
        float2 v = ((const float2*)(g_agg0 + (size_t)idx * K))[lane];
        s0 += v.x; s1 += v.y;
        q0 += v.x * v.x; q1 += v.y * v.y;
    }

    // item embedding lookup + renorm
    int it = __ldg(item_ids + warp);
    float2 t = __ldg((const float2*)(ent + (size_t)it * K) + lane);
    float ts  = warp_sum(t.x * t.x + t.y * t.y);
    float tsc = ts > 1.f ? rsqrtf(ts) : 1.f;

    float i0 = s0 * s0 - q0 + t.x * tsc;
    float i1 = s1 * s1 - q1 + t.y * tsc;

    // user embedding lookup + renorm
    int uu = __ldg(u + warp);
    float2 uv = __ldg((const float2*)(uemb + (size_t)uu * K) + lane);
    float us  = warp_sum(uv.x * uv.x + uv.y * uv.y);
    float usc = us > 1.f ? rsqrtf(us) : 1.f;

    float dot = warp_sum(uv.x * usc * i0 + uv.y * usc * i1);
    if (lane == 0) out[warp] = 1.f / (1.f + expf(-dot));
}

extern "C" void kernel_launch(void* const* d_in, const int* in_sizes, int n_in,
                              void* d_out, int out_size)
{
    const float* ent       = (const float*)d_in[0];   // entity_emb [1e6, 64]
    const float* uemb      = (const float*)d_in[1];   // user_emb   [1e5, 64]
    // d_in[2..5]: Wa, ba, Wh, bh — dead (softmax over singleton == 1)
    const int*   u         = (const int*)d_in[6];     // [B]
    const int*   item_ids  = (const int*)d_in[7];     // [B]
    const int*   nbr1      = (const int*)d_in[8];     // [B, DEG]
    const int*   node_ids0 = (const int*)d_in[9];     // [N0]
    const int*   nbr0      = (const int*)d_in[10];    // [N0, DEG]
    float*       out       = (float*)d_out;           // [B]

    hop0_kernel<<<N0 / 8, 256>>>(ent, node_ids0, nbr0);          // 65536 warps
    hop1_kernel<<<B  / 8, 256>>>(ent, uemb, u, item_ids, nbr1, out); // 2048 warps
}

// round 3
// speedup vs baseline: 1.1464x; 1.1464x over previous
#include <cuda_runtime.h>

// GAFM reduced form (softmax over singleton axis == 1 -> attention MLP dead):
//   hop0: agg0[j] = FM(renorm(E[nbr0[j,:]])) + renorm(E[node_ids0[j]])
//   hop1: items   = FM(agg0[nbr1_idx[i,:]]) + renorm(E[item_ids[i]])
//         logit_i = sigmoid(<renorm(U[u[i]]), items>)

constexpr int K    = 64;
constexpr int B    = 2048;
constexpr int DEG  = 32;
constexpr int N0   = B * DEG;   // 65536

__device__ float g_agg0[(size_t)N0 * K];   // 16 MB scratch

__device__ __forceinline__ float warp_sum(float v) {
#pragma unroll
    for (int o = 16; o; o >>= 1) v += __shfl_xor_sync(0xffffffffu, v, o);
    return v;
}

// ---------------- hop 0: one warp per frontier node ----------------
// Lane l owns dims {2l, 2l+1}. Loads are staged 8-wide to raise MLP.
__global__ void __launch_bounds__(256) hop0_kernel(
    const float* __restrict__ ent,
    const int*   __restrict__ node_ids0,
    const int*   __restrict__ nbr0)
{
    int warp = (blockIdx.x * blockDim.x + threadIdx.x) >> 5;
    int lane = threadIdx.x & 31;
    if (warp >= N0) return;

    int myn = __ldg(nbr0 + warp * DEG + lane);   // lane i holds neighbor i

    // prefetch target row early (independent of the loop)
    int nid = __ldg(node_ids0 + warp);
    float2 t = __ldg((const float2*)(ent + (size_t)nid * K) + lane);

    float s0 = 0.f, s1 = 0.f, q0 = 0.f, q1 = 0.f;
#pragma unroll
    for (int base = 0; base < DEG; base += 8) {
        float2 v[8];
#pragma unroll
        for (int g = 0; g < 8; ++g) {
            int idx = __shfl_sync(0xffffffffu, myn, base + g);
            v[g] = __ldg((const float2*)(ent + (size_t)idx * K) + lane);
        }
#pragma unroll
        for (int g = 0; g < 8; ++g) {
            float ss = warp_sum(v[g].x * v[g].x + v[g].y * v[g].y);
            float sc = ss > 1.f ? rsqrtf(ss) : 1.f;     // min(1, 1/||row||)
            float x0 = v[g].x * sc, x1 = v[g].y * sc;
            s0 += x0; s1 += x1;
            q0 += x0 * x0; q1 += x1 * x1;
        }
    }

    float ts  = warp_sum(t.x * t.x + t.y * t.y);
    float tsc = ts > 1.f ? rsqrtf(ts) : 1.f;

    float2 o;
    o.x = s0 * s0 - q0 + t.x * tsc;
    o.y = s1 * s1 - q1 + t.y * tsc;
    ((float2*)(g_agg0 + (size_t)warp * K))[lane] = o;
}

// ---------------- hop 1: one block (4 warps) per batch item ----------------
// Each warp gathers 8 neighbors; partial (s,q) combined through smem.
__global__ void __launch_bounds__(128) hop1_kernel(
    const float* __restrict__ ent,
    const float* __restrict__ uemb,
    const int*   __restrict__ u,
    const int*   __restrict__ item_ids,
    const int*   __restrict__ nbr1,
    float*       __restrict__ out)
{
    __shared__ float4 part[4][32];   // per-warp per-lane {s0,s1,q0,q1}

    int item = blockIdx.x;
    int w    = threadIdx.x >> 5;
    int lane = threadIdx.x & 31;

    // warp w handles neighbors [8w, 8w+8); lanes 0..7 hold the indices
    int myn = 0;
    if (lane < 8) myn = __ldg(nbr1 + item * DEG + w * 8 + lane);

    // warp 0 prefetches item/user rows while all warps gather
    float2 t = make_float2(0.f, 0.f), uv = make_float2(0.f, 0.f);
    if (w == 0) {
        int it = __ldg(item_ids + item);
        int uu = __ldg(u + item);
        t  = __ldg((const float2*)(ent  + (size_t)it * K) + lane);
        uv = __ldg((const float2*)(uemb + (size_t)uu * K) + lane);
    }

    float2 v[8];
#pragma unroll
    for (int g = 0; g < 8; ++g) {
        int idx = __shfl_sync(0xffffffffu, myn, g);
        v[g] = ((const float2*)(g_agg0 + (size_t)idx * K))[lane];
    }
    float s0 = 0.f, s1 = 0.f, q0 = 0.f, q1 = 0.f;
#pragma unroll
    for (int g = 0; g < 8; ++g) {
        s0 += v[g].x; s1 += v[g].y;
        q0 += v[g].x * v[g].x; q1 += v[g].y * v[g].y;
    }
    part[w][lane] = make_float4(s0, s1, q0, q1);
    __syncthreads();

    if (w == 0) {
        float4 a = part[0][lane], b = part[1][lane],
               c = part[2][lane], d = part[3][lane];
        float S0 = a.x + b.x + c.x + d.x;
        float S1 = a.y + b.y + c.y + d.y;
        float Q0 = a.z + b.z + c.z + d.z;
        float Q1 = a.w + b.w + c.w + d.w;

        float ts  = warp_sum(t.x * t.x + t.y * t.y);
        float tsc = ts > 1.f ? rsqrtf(ts) : 1.f;
        float i0 = S0 * S0 - Q0 + t.x * tsc;
        float i1 = S1 * S1 - Q1 + t.y * tsc;

        float us  = warp_sum(uv.x * uv.x + uv.y * uv.y);
        float usc = us > 1.f ? rsqrtf(us) : 1.f;

        float dot = warp_sum(uv.x * usc * i0 + uv.y * usc * i1);
        if (lane == 0) out[item] = 1.f / (1.f + expf(-dot));
    }
}

extern "C" void kernel_launch(void* const* d_in, const int* in_sizes, int n_in,
                              void* d_out, int out_size)
{
    const float* ent       = (const float*)d_in[0];
    const float* uemb      = (const float*)d_in[1];
    // d_in[2..5]: Wa, ba, Wh, bh — dead
    const int*   u         = (const int*)d_in[6];
    const int*   item_ids  = (const int*)d_in[7];
    const int*   nbr1      = (const int*)d_in[8];
    const int*   node_ids0 = (const int*)d_in[9];
    const int*   nbr0      = (const int*)d_in[10];
    float*       out       = (float*)d_out;

    hop0_kernel<<<N0 / 8, 256>>>(ent, node_ids0, nbr0);
    hop1_kernel<<<B, 128>>>(ent, uemb, u, item_ids, nbr1, out);
}